// round 10
// baseline (speedup 1.0000x reference)
#include <cuda_runtime.h>
#include <cstdint>

// Problem constants (shapes fixed by the dataset)
#define BB    64
#define KK    8
#define VV    128000
#define TPB   256
#define NW    8              // warps per block
#define BPB   4              // blocks per batch
#define FPB   32000          // floats per block span (per row)
#define NSTG  10             // pipeline stages per block
#define SPS   25             // segments per stage
#define SEG_F 128            // floats per segment
#define STG_F (SPS * SEG_F)  // 3200 floats per stage
#define STG_B (STG_F * 4)    // 12800 bytes per stage per row
#define SEGS_BATCH 1000      // 128000 / 128
#define STAGES_BATCH (BPB * NSTG)   // 40
#define FULL 0xFFFFFFFFu

// Scratch (device globals — zero-initialized; g_done self-resets every call)
__device__ float g_segsum[BB * SEGS_BATCH];
__device__ float g_stagesum[BB * STAGES_BATCH];
__device__ int   g_done[BB];

__device__ __forceinline__ uint32_t smem_u32(const void* p) {
    uint32_t a;
    asm("{ .reg .u64 t; cvta.to.shared.u64 t, %1; cvt.u32.u64 %0, t; }"
        : "=r"(a) : "l"(p));
    return a;
}

__device__ __forceinline__ void mbar_wait(uint32_t mb, uint32_t parity) {
    asm volatile(
        "{\n\t.reg .pred P1;\n\t"
        "W%=:\n\t"
        "mbarrier.try_wait.parity.acquire.cta.shared::cta.b64 P1, [%0], %1, 0x989680;\n\t"
        "@P1 bra D%=;\n\t"
        "bra W%=;\n\t"
        "D%=:\n\t}"
        :: "r"(mb), "r"(parity) : "memory");
}

__device__ __forceinline__ void tma_1d(uint32_t dst, const void* src,
                                       uint32_t bytes, uint32_t mb) {
    asm volatile(
        "cp.async.bulk.shared::cluster.global.mbarrier::complete_tx::bytes "
        "[%0], [%1], %2, [%3];"
        :: "r"(dst), "l"(src), "r"(bytes), "r"(mb) : "memory");
}

// ---------------------------------------------------------------------------
// Pipelined fused kernel. grid = 256 (single wave, all CTAs resident).
// Per block: acceptance once, then 10 stages of (TMA-prefetched smem compute)
// with a 2-deep buffer — fetch of stage i+2 overlaps compute of stage i.
// ---------------------------------------------------------------------------
__global__ void __launch_bounds__(TPB)
k_fused(const int*   __restrict__ dtok,
        const float* __restrict__ dp,
        const float* __restrict__ op,
        const float* __restrict__ unif,
        const float* __restrict__ su,
        float*       __restrict__ out)
{
    extern __shared__ float sm[];          // [buf0: o 3200 | d 3200][buf1: ...]
    __shared__ alignas(8) unsigned long long mbar[2];
    __shared__ float ssh[2][SPS];
    __shared__ int   sh_na, sh_last;

    int blk = blockIdx.x;
    int b = blk / BPB, g = blk % BPB;
    int t = threadIdx.x, lane = t & 31, wid = t >> 5;

    // ---- acceptance (warp 0) + mbarrier init ----
    if (wid == 0) {
        bool acc = false;
        if (lane < KK) {
            int tok  = dtok[b * KK + lane];
            float pd = dp[(b * KK + lane) * VV + tok];
            float po = op[(b * (KK + 1) + lane) * VV + tok];
            acc = unif[b * KK + lane] < fminf(1.0f, po / pd);
        }
        unsigned bits = __ballot_sync(FULL, acc) & ((1u << KK) - 1u);
        if (lane == 0) {
            sh_na = __ffs(~bits) - 1;
            asm volatile("mbarrier.init.shared.b64 [%0], %1;"
                         :: "r"(smem_u32(&mbar[0])), "r"(1) : "memory");
            asm volatile("mbarrier.init.shared.b64 [%0], %1;"
                         :: "r"(smem_u32(&mbar[1])), "r"(1) : "memory");
        }
    }
    __syncthreads();
    int na     = sh_na;
    int allacc = (na == KK);
    int r      = min(na, KK - 1);

    const float* orow = op + (b * (KK + 1) + (allacc ? KK : r)) * VV + g * FPB;
    const float* drow = dp + (b * KK + r) * VV + g * FPB;
    uint32_t tx_bytes = allacc ? STG_B : 2u * STG_B;

    // ---- prologue: prefetch stages 0 and 1 ----
    if (t == 0) {
#pragma unroll
        for (int p = 0; p < 2; ++p) {
            uint32_t mb = smem_u32(&mbar[p]);
            asm volatile("mbarrier.arrive.expect_tx.shared.b64 _, [%0], %1;"
                         :: "r"(mb), "r"(tx_bytes) : "memory");
            tma_1d(smem_u32(sm + p * 2 * STG_F), orow + p * STG_F, STG_B, mb);
            if (!allacc)
                tma_1d(smem_u32(sm + p * 2 * STG_F + STG_F), drow + p * STG_F,
                       STG_B, mb);
        }
    }

    // ---- token scaffolding overlapped with first TMA (block g==0 only) ----
    if (g == 0) {
        if (t <= KK && t != na)
            out[b * (KK + 1) + t] = (t < na) ? (float)dtok[b * KK + t] : -1.0f;
        if (t == KK + 1)
            out[BB * (KK + 1) + b] = (float)na;
    }

    // ---- pipelined mainloop ----
    int ph0 = 0, ph1 = 0;
    for (int i = 0; i < NSTG; ++i) {
        int k = i & 1;
        if (k == 0) { mbar_wait(smem_u32(&mbar[0]), ph0); ph0 ^= 1; }
        else        { mbar_wait(smem_u32(&mbar[1]), ph1); ph1 ^= 1; }

        const float4* o4 = (const float4*)(sm + k * 2 * STG_F);
        const float4* d4 = (const float4*)(sm + k * 2 * STG_F + STG_F);
        for (int j = wid; j < SPS; j += NW) {
            float4 a = o4[j * 32 + lane];
            float p;
            if (allacc) {
                p = a.x + a.y + a.z + a.w;
            } else {
                float4 e = d4[j * 32 + lane];
                p = fmaxf(a.x - e.x, 0.f) + fmaxf(a.y - e.y, 0.f)
                  + fmaxf(a.z - e.z, 0.f) + fmaxf(a.w - e.w, 0.f);
            }
#pragma unroll
            for (int o = 16; o > 0; o >>= 1)
                p += __shfl_down_sync(FULL, p, o);
            if (lane == 0) {
                ssh[k][j] = p;
                g_segsum[b * SEGS_BATCH + g * (NSTG * SPS) + i * SPS + j] = p;
            }
        }
        __syncthreads();               // all reads of buf k complete
        if (t == 0) {
            float c = 0.0f;            // sequential: matches level-2 scan order
#pragma unroll
            for (int j = 0; j < SPS; ++j) c += ssh[k][j];
            g_stagesum[b * STAGES_BATCH + g * NSTG + i] = c;
            int nxt = i + 2;
            if (nxt < NSTG) {          // refill this buffer
                uint32_t mb = smem_u32(&mbar[k]);
                asm volatile("mbarrier.arrive.expect_tx.shared.b64 _, [%0], %1;"
                             :: "r"(mb), "r"(tx_bytes) : "memory");
                tma_1d(smem_u32(sm + k * 2 * STG_F), orow + nxt * STG_F, STG_B, mb);
                if (!allacc)
                    tma_1d(smem_u32(sm + k * 2 * STG_F + STG_F),
                           drow + nxt * STG_F, STG_B, mb);
            }
        }
    }

    // ---- publish + elect last block of this batch ----
    __syncthreads();
    if (t == 0) {
        __threadfence();
        int old = atomicAdd(&g_done[b], 1);
        sh_last = (old == BPB - 1);
        if (sh_last) g_done[b] = 0;    // self-reset for graph replay
    }
    __syncthreads();
    if (!sh_last || wid != 0) return;

    __threadfence();                    // acquire before cross-block reads

    // ---- level 1: 40 stage sums ----
    float s0 = __ldcg(&g_stagesum[b * STAGES_BATCH + lane]);
    float s1 = (lane < 8) ? __ldcg(&g_stagesum[b * STAGES_BATCH + 32 + lane]) : 0.0f;
    float x0 = s0, x1 = s1;
#pragma unroll
    for (int o = 1; o < 32; o <<= 1) {
        float y0 = __shfl_up_sync(FULL, x0, o);
        float y1 = __shfl_up_sync(FULL, x1, o);
        if (lane >= o) { x0 += y0; x1 += y1; }
    }
    float x0_31 = __shfl_sync(FULL, x0, 31);
    float tot   = x0_31 + __shfl_sync(FULL, x1, 31);
    float T = allacc ? su[b] : su[b] * tot;

    int st = -1;
    float base = 0.0f;
    unsigned b0 = __ballot_sync(FULL, x0 >= T);
    if (b0) {
        int l = __ffs(b0) - 1;
        st = l;
        base = __shfl_sync(FULL, x0, l) - __shfl_sync(FULL, s0, l);
    } else {
        unsigned b1 = __ballot_sync(FULL, (lane < 8) && (x0_31 + x1 >= T));
        if (b1) {
            int l = __ffs(b1) - 1;
            st = 32 + l;
            base = x0_31 + __shfl_sync(FULL, x1, l) - __shfl_sync(FULL, s1, l);
        }
    }

    int token;
    if (st < 0) {
        token = VV - 1;                       // u beyond total mass
    } else {
        // ---- level 2: 25 segment sums of stage st ----
        float ss = (lane < SPS)
                 ? __ldcg(&g_segsum[b * SEGS_BATCH + st * SPS + lane]) : 0.0f;
        float xx = ss;
#pragma unroll
        for (int o = 1; o < 32; o <<= 1) {
            float y = __shfl_up_sync(FULL, xx, o);
            if (lane >= o) xx += y;
        }
        unsigned b2 = __ballot_sync(FULL, (lane < SPS) && (base + xx >= T));
        if (!b2) {
            token = min((st + 1) * STG_F, VV - 1);     // ulp-tie fallback
        } else {
            int j = __ffs(b2) - 1;
            float base_t = base + __shfl_sync(FULL, xx, j)
                                - __shfl_sync(FULL, ss, j);

            // ---- level 3: one 128-float segment, coalesced re-read ----
            int off0 = (st * SPS + j) * SEG_F;
            int ob2  = (b * (KK + 1) + (allacc ? KK : r)) * VV + off0;
            int db2  = (b * KK + r) * VV + off0;
            float4 ov = ((const float4*)(op + ob2))[lane];
            float v0, v1, v2, v3;
            if (allacc) {
                v0 = ov.x; v1 = ov.y; v2 = ov.z; v3 = ov.w;
            } else {
                float4 dv = ((const float4*)(dp + db2))[lane];
                v0 = fmaxf(ov.x - dv.x, 0.f); v1 = fmaxf(ov.y - dv.y, 0.f);
                v2 = fmaxf(ov.z - dv.z, 0.f); v3 = fmaxf(ov.w - dv.w, 0.f);
            }
            float local = v0 + v1 + v2 + v3;
            float xs = local;
#pragma unroll
            for (int o = 1; o < 32; o <<= 1) {
                float y = __shfl_up_sync(FULL, xs, o);
                if (lane >= o) xs += y;
            }
            unsigned b3 = __ballot_sync(FULL, base_t + xs >= T);
            if (!b3) {
                token = min(off0 + SEG_F, VV - 1);      // ulp-tie fallback
            } else {
                int l = __ffs(b3) - 1;
                float excl = base_t + __shfl_sync(FULL, xs, l)
                                    - __shfl_sync(FULL, local, l);
                float a0 = __shfl_sync(FULL, v0, l);
                float a1 = __shfl_sync(FULL, v1, l);
                float a2 = __shfl_sync(FULL, v2, l);
                float run = excl;
                int idx = 3;
                run += a0;
                if (run >= T) idx = 0;
                else { run += a1;
                    if (run >= T) idx = 1;
                    else { run += a2; if (run >= T) idx = 2; }
                }
                token = min(off0 + l * 4 + idx, VV - 1);
            }
        }
    }

    if (lane == 0)
        out[b * (KK + 1) + na] = (float)token;
}

// ---------------------------------------------------------------------------
// Host launcher: classify inputs by element count (order-agnostic).
// ---------------------------------------------------------------------------
extern "C" void kernel_launch(void* const* d_in, const int* in_sizes, int n_in,
                              void* d_out, int out_size)
{
    const int*   dtok = nullptr;
    const float* dp   = nullptr;
    const float* op   = nullptr;
    const float* unif = nullptr;
    const float* su   = nullptr;

    int n512 = 0;
    for (int i = 0; i < n_in; ++i) {
        long sz = (long)in_sizes[i];
        if (sz == (long)BB * KK * VV)            dp = (const float*)d_in[i];
        else if (sz == (long)BB * (KK + 1) * VV) op = (const float*)d_in[i];
        else if (sz == BB)                       su = (const float*)d_in[i];
        else if (sz == BB * KK) {
            // relative order: draft_tokens, oracle_tokens, uniforms
            if      (n512 == 0) dtok = (const int*)d_in[i];
            else if (n512 == 2) unif = (const float*)d_in[i];
            ++n512;
        }
    }

    float* out = (float*)d_out;  // [tokens (B*(K+1)) | num_accepted (B)] as f32

    const int smem_bytes = 4 * STG_F * (int)sizeof(float);   // 51 200 B
    static bool configured = false;
    if (!configured) {
        cudaFuncSetAttribute(k_fused, cudaFuncAttributeMaxDynamicSharedMemorySize,
                             smem_bytes);
        configured = true;
    }
    k_fused<<<BB * BPB, TPB, smem_bytes>>>(dtok, dp, op, unif, su, out);
}

// round 11
// speedup vs baseline: 1.2691x; 1.2691x over previous
#include <cuda_runtime.h>
#include <cstdint>

// Problem constants (shapes fixed by the dataset)
#define BB   64
#define KK   8
#define VV   128000
#define NS   25              // chunks per batch row
#define TPB  256
#define NW   (TPB / 32)      // 8 warps per block
#define LCH  (VV / NS)       // 5120 floats per chunk
#define SEG  128             // floats per segment (one warp-wide float4 iter)
#define SPW  5               // segments per warp (5*128 = 640 floats)
#define SEGS (NW * SPW)      // 40 segments per chunk
#define FULL 0xFFFFFFFFu

// Scratch (device globals — zero-initialized; g_done self-resets every call)
__device__ float g_ssum[BB * NS * SEGS];     // per-segment sums (256 KB)
__device__ float g_chunksum[BB * NS];
__device__ int   g_done[BB];

__device__ __forceinline__ uint32_t smem_u32(const void* p) {
    uint32_t a;
    asm("{ .reg .u64 t; cvta.to.shared.u64 t, %1; cvt.u32.u64 %0, t; }"
        : "=r"(a) : "l"(p));
    return a;
}

// ---------------------------------------------------------------------------
// Hierarchical CDF search for one batch (one warp) — identical to round 7.
// level 1: 25 chunk sums -> level 2: 40 segment sums -> level 3: 128 floats.
// ---------------------------------------------------------------------------
__device__ __forceinline__ void cdf_search(int b, int na, int allacc, int r,
                                           const float* __restrict__ dp,
                                           const float* __restrict__ op,
                                           const float* __restrict__ su,
                                           float* __restrict__ out, int lane)
{
    float cs = (lane < NS) ? __ldcg(&g_chunksum[b * NS + lane]) : 0.0f;
    float x = cs;
#pragma unroll
    for (int o = 1; o < 32; o <<= 1) {
        float y = __shfl_up_sync(FULL, x, o);
        if (lane >= o) x += y;
    }
    float tot = __shfl_sync(FULL, x, NS - 1);
    float T = allacc ? su[b] : su[b] * tot;

    unsigned bal = __ballot_sync(FULL, (lane < NS) && (x >= T));
    int token;
    if (bal == 0) {
        token = VV - 1;
    } else {
        int sc = __ffs(bal) - 1;
        float base = __shfl_sync(FULL, x, sc) - __shfl_sync(FULL, cs, sc);

        const float* ss = &g_ssum[(b * NS + sc) * SEGS];
        int   j_found = -1;
        float base_t  = 0.0f;
        float running = base;
#pragma unroll
        for (int g = 0; g < 2; ++g) {
            int j = g * 32 + lane;
            float v = (j < SEGS) ? __ldcg(&ss[j]) : 0.0f;
            float xx = v;
#pragma unroll
            for (int o = 1; o < 32; o <<= 1) {
                float y = __shfl_up_sync(FULL, xx, o);
                if (lane >= o) xx += y;
            }
            unsigned bb2 = __ballot_sync(FULL, (j < SEGS) && (running + xx >= T));
            if (bb2) {
                int l = __ffs(bb2) - 1;
                j_found = g * 32 + l;
                base_t  = running + __shfl_sync(FULL, xx, l)
                                  - __shfl_sync(FULL, v, l);
                break;
            }
            running += __shfl_sync(FULL, xx, 31);
        }

        if (j_found < 0) {
            token = min(sc * LCH + LCH, VV - 1);         // ulp-tie fallback
        } else {
            int off0 = sc * LCH + j_found * SEG;
            int ob2  = (b * (KK + 1) + (allacc ? KK : r)) * VV + off0;
            int db2  = (b * KK + r) * VV + off0;
            float4 ov = ((const float4*)(op + ob2))[lane];
            float v0, v1, v2, v3;
            if (allacc) {
                v0 = ov.x; v1 = ov.y; v2 = ov.z; v3 = ov.w;
            } else {
                float4 dv = ((const float4*)(dp + db2))[lane];
                v0 = fmaxf(ov.x - dv.x, 0.f); v1 = fmaxf(ov.y - dv.y, 0.f);
                v2 = fmaxf(ov.z - dv.z, 0.f); v3 = fmaxf(ov.w - dv.w, 0.f);
            }
            float local = v0 + v1 + v2 + v3;
            float xx = local;
#pragma unroll
            for (int o = 1; o < 32; o <<= 1) {
                float y = __shfl_up_sync(FULL, xx, o);
                if (lane >= o) xx += y;
            }
            unsigned bb3 = __ballot_sync(FULL, base_t + xx >= T);
            if (!bb3) {
                token = min(off0 + SEG, VV - 1);          // ulp-tie fallback
            } else {
                int l = __ffs(bb3) - 1;
                float excl = base_t + __shfl_sync(FULL, xx, l)
                                    - __shfl_sync(FULL, local, l);
                float a0 = __shfl_sync(FULL, v0, l);
                float a1 = __shfl_sync(FULL, v1, l);
                float a2 = __shfl_sync(FULL, v2, l);
                float run = excl;
                int idx = 3;
                run += a0;
                if (run >= T) idx = 0;
                else { run += a1;
                    if (run >= T) idx = 1;
                    else { run += a2; if (run >= T) idx = 2; }
                }
                token = min(off0 + l * 4 + idx, VV - 1);
            }
        }
    }

    if (lane == 0)
        out[b * (KK + 1) + na] = (float)token;
}

// ---------------------------------------------------------------------------
// Fused kernel (round-7 skeleton): one chunk per block, grid = 1600.
// Dual-path streaming: oracle row via LDG.128 into registers, draft row via
// cp.async.cg into shared memory (zero destination registers). Both streams
// fully in flight at ~35 regs -> 6-7 resident blocks/SM.
// ---------------------------------------------------------------------------
__global__ void __launch_bounds__(TPB, 6)
k_fused(const int*   __restrict__ dtok,
        const float* __restrict__ dp,
        const float* __restrict__ op,
        const float* __restrict__ unif,
        const float* __restrict__ su,
        float*       __restrict__ out)
{
    __shared__ alignas(16) float sh_d[LCH];      // 20 KB draft-row stage
    __shared__ float ssh[SEGS];

    int blk = blockIdx.x;
    int b = blk / NS, s = blk % NS;
    int t = threadIdx.x, lane = t & 31, wid = t >> 5;

    // ---- acceptance, computed redundantly per warp (L2-hot) ----
    bool acc = false;
    if (lane < KK) {
        int tok  = dtok[b * KK + lane];
        float pd = dp[(b * KK + lane) * VV + tok];
        float po = op[(b * (KK + 1) + lane) * VV + tok];
        acc = unif[b * KK + lane] < fminf(1.0f, po / pd);
    }
    unsigned bits = __ballot_sync(FULL, acc) & ((1u << KK) - 1u);
    int na     = __ffs(~bits) - 1;          // 8 if all accepted
    int allacc = (na == KK);
    int r      = min(na, KK - 1);

    // ---- dual-path streaming ----
    int row    = s * LCH;                    // chunk offset within the row
    const float4* o4 = (const float4*)(op + (b * (KK + 1) + (allacc ? KK : r)) * VV + row);
    const float4* d4 = (const float4*)(dp + (b * KK + r) * VV + row);
    int base = wid * (SPW * 32);             // this warp's float4 index base

    if (!allacc) {
        uint32_t sbase = smem_u32(sh_d);
#pragma unroll
        for (int i = 0; i < SPW; ++i) {
            int idx = base + i * 32 + lane;
            uint32_t dst = sbase + (uint32_t)idx * 16u;
            asm volatile("cp.async.cg.shared.global [%0], [%1], 16;"
                         :: "r"(dst), "l"(d4 + idx) : "memory");
        }
        asm volatile("cp.async.commit_group;" ::: "memory");
    }

    float4 a0 = o4[base + 0 * 32 + lane];
    float4 a1 = o4[base + 1 * 32 + lane];
    float4 a2 = o4[base + 2 * 32 + lane];
    float4 a3 = o4[base + 3 * 32 + lane];
    float4 a4 = o4[base + 4 * 32 + lane];

    float p[SPW];
    if (allacc) {
        p[0] = a0.x + a0.y + a0.z + a0.w;
        p[1] = a1.x + a1.y + a1.z + a1.w;
        p[2] = a2.x + a2.y + a2.z + a2.w;
        p[3] = a3.x + a3.y + a3.z + a3.w;
        p[4] = a4.x + a4.y + a4.z + a4.w;
    } else {
        // each lane reads back exactly the 16B it copied -> wait_group suffices
        asm volatile("cp.async.wait_group 0;" ::: "memory");
        const float4* sd4 = (const float4*)sh_d;
        float4 e0 = sd4[base + 0 * 32 + lane];
        float4 e1 = sd4[base + 1 * 32 + lane];
        float4 e2 = sd4[base + 2 * 32 + lane];
        float4 e3 = sd4[base + 3 * 32 + lane];
        float4 e4 = sd4[base + 4 * 32 + lane];
        p[0] = fmaxf(a0.x - e0.x, 0.f) + fmaxf(a0.y - e0.y, 0.f)
             + fmaxf(a0.z - e0.z, 0.f) + fmaxf(a0.w - e0.w, 0.f);
        p[1] = fmaxf(a1.x - e1.x, 0.f) + fmaxf(a1.y - e1.y, 0.f)
             + fmaxf(a1.z - e1.z, 0.f) + fmaxf(a1.w - e1.w, 0.f);
        p[2] = fmaxf(a2.x - e2.x, 0.f) + fmaxf(a2.y - e2.y, 0.f)
             + fmaxf(a2.z - e2.z, 0.f) + fmaxf(a2.w - e2.w, 0.f);
        p[3] = fmaxf(a3.x - e3.x, 0.f) + fmaxf(a3.y - e3.y, 0.f)
             + fmaxf(a3.z - e3.z, 0.f) + fmaxf(a3.w - e3.w, 0.f);
        p[4] = fmaxf(a4.x - e4.x, 0.f) + fmaxf(a4.y - e4.y, 0.f)
             + fmaxf(a4.z - e4.z, 0.f) + fmaxf(a4.w - e4.w, 0.f);
    }

    // ---- segment sums (warp tree-reduce), shared + global ----
#pragma unroll
    for (int i = 0; i < SPW; ++i) {
        float w = p[i];
#pragma unroll
        for (int o = 16; o > 0; o >>= 1)
            w += __shfl_down_sync(FULL, w, o);
        if (lane == 0) {
            ssh[wid * SPW + i] = w;
            g_ssum[blk * SEGS + wid * SPW + i] = w;
        }
    }

    // ---- token scaffolding (chunk s==0 writes all slots except na) ----
    if (s == 0) {
        if (t <= KK && t != na)
            out[b * (KK + 1) + t] = (t < na) ? (float)dtok[b * KK + t] : -1.0f;
        if (t == KK + 1)
            out[BB * (KK + 1) + b] = (float)na;
    }

    __syncthreads();
    if (t == 0) {                     // sequential order == level-2 scan order
        float c = 0.0f;
#pragma unroll
        for (int j = 0; j < SEGS; ++j) c += ssh[j];
        g_chunksum[blk] = c;
    }

    // ---- publish + elect last block of this batch ----
    __shared__ int sh_last;
    __syncthreads();
    if (t == 0) {
        __threadfence();              // make g_ssum/g_chunksum device-visible
        int old = atomicAdd(&g_done[b], 1);
        sh_last = (old == NS - 1);
        if (sh_last) g_done[b] = 0;   // self-reset for graph replay
    }
    __syncthreads();
    if (!sh_last || wid != 0) return;

    __threadfence();                  // acquire before cross-block reads
    cdf_search(b, na, allacc, r, dp, op, su, out, lane);
}

// ---------------------------------------------------------------------------
// Host launcher: classify inputs by element count (order-agnostic).
// ---------------------------------------------------------------------------
extern "C" void kernel_launch(void* const* d_in, const int* in_sizes, int n_in,
                              void* d_out, int out_size)
{
    const int*   dtok = nullptr;
    const float* dp   = nullptr;
    const float* op   = nullptr;
    const float* unif = nullptr;
    const float* su   = nullptr;

    int n512 = 0;
    for (int i = 0; i < n_in; ++i) {
        long sz = (long)in_sizes[i];
        if (sz == (long)BB * KK * VV)            dp = (const float*)d_in[i];
        else if (sz == (long)BB * (KK + 1) * VV) op = (const float*)d_in[i];
        else if (sz == BB)                       su = (const float*)d_in[i];
        else if (sz == BB * KK) {
            // relative order: draft_tokens, oracle_tokens, uniforms
            if      (n512 == 0) dtok = (const int*)d_in[i];
            else if (n512 == 2) unif = (const float*)d_in[i];
            ++n512;
        }
    }

    float* out = (float*)d_out;  // [tokens (B*(K+1)) | num_accepted (B)] as f32

    k_fused<<<BB * NS, TPB>>>(dtok, dp, op, unif, su, out);
}